// round 10
// baseline (speedup 1.0000x reference)
#include <cuda_runtime.h>
#include <cuda_bf16.h>
#include <cuda_fp16.h>
#include <cstdint>
#include <math.h>

#define BQ   32
#define TT   128
#define EE   256
#define HH   512
#define ENCC 512
#define VV   10000
#define G4   2048          // 4*H
#define XW   1280          // E + H + ENC
#define VPAD 10112         // 79 * 128

// ------------------------------------------------------------------
// scratch (static device globals; no allocations allowed)
// ------------------------------------------------------------------
__device__ float g_o[BQ * HH];
__device__ float g_c0[BQ * HH];
__device__ float g_base[BQ * G4];
__device__ float g_G[TT * BQ * G4];               // per-step gate input (32 MB)
__device__ unsigned g_bar_count;
__device__ unsigned g_bar_gen;

// fp16 operands
__device__ __half g_h16[(TT + 1) * BQ * HH];      // slot0=h0, slot t+1 = h after step t
__device__ __half g_Bh[VPAD * HH];                // logits B (Wv) fp16
__device__ __half g_E[TT * BQ * EE];              // gathered prev-token embeddings
__device__ __half g_Wih16[G4 * EE];               // W_ih[:, :E] fp16
__device__ __half g_Wihb[G4 * 1024];              // W_ih[:, E:] fp16
__device__ __half g_Whh16[G4 * HH];               // W_hh fp16
__device__ __half g_X16[128 * 1024];              // [o|tv] fp16, rows 32..127 zero

// ------------------------------------------------------------------
// kernel 1: o, h0, c0   (warp per output, shuffle reduce)
// ------------------------------------------------------------------
__global__ void k_init(const float* __restrict__ tv,
                       const float* __restrict__ Wo, const float* __restrict__ bo,
                       const float* __restrict__ Wh, const float* __restrict__ bh,
                       const float* __restrict__ Wc, const float* __restrict__ bc)
{
    int warp = (blockIdx.x * blockDim.x + threadIdx.x) >> 5;
    int lane = threadIdx.x & 31;
    if (warp >= 3 * BQ * HH) return;
    int m   = warp / (BQ * HH);
    int rem = warp % (BQ * HH);
    int b = rem / HH, j = rem % HH;
    const float* W    = (m == 0) ? Wo : (m == 1) ? Wh : Wc;
    const float* bias = (m == 0) ? bo : (m == 1) ? bh : bc;
    const float* x = tv + b * ENCC;
    const float* w = W  + j * ENCC;
    float s = 0.f;
    for (int k = lane; k < ENCC; k += 32) s += x[k] * w[k];
    #pragma unroll
    for (int o = 16; o; o >>= 1) s += __shfl_xor_sync(0xffffffffu, s, o);
    if (lane == 0) {
        float v = s + bias[j];
        if (m == 0)      g_o[b * HH + j]   = v;
        else if (m == 1) g_h16[b * HH + j] = __float2half_rn(v);   // slot 0 = h0
        else             g_c0[b * HH + j]  = v;
    }
}

// ------------------------------------------------------------------
// kernel 2a: pack A = [o | tv] fp16 into g_X16 rows 0..31
// ------------------------------------------------------------------
__global__ void k_packX(const float* __restrict__ tv)
{
    int e = (blockIdx.x * 256 + threadIdx.x) * 2;    // 32x1024 elems
    int b = e >> 10, c = e & 1023;
    float v0, v1;
    if (c < 512) { v0 = g_o[b * HH + c];        v1 = g_o[b * HH + c + 1]; }
    else         { v0 = tv[b * ENCC + c - 512]; v1 = tv[b * ENCC + c - 511]; }
    *(__half2*)(g_X16 + b * 1024 + c) = __floats2half2_rn(v0, v1);
}

// ------------------------------------------------------------------
// kernel 3a: gather prev-token embeddings as dense fp16 A [4096 x 256]
// ------------------------------------------------------------------
__global__ void k_gather(const float* __restrict__ emb,
                         const int*   __restrict__ texts,
                         const int*   __restrict__ startp)
{
    int r = blockIdx.x;                 // 0..4095
    int t = r >> 5, b = r & 31;
    int tok = (t == 0) ? startp[0] : texts[b * TT + t - 1];
    const float* src = emb + (size_t)tok * EE;
    int k = threadIdx.x * 4;            // 64 threads x 4
    float4 v = *(const float4*)(src + k);
    *(__half2*)(g_E + (size_t)r * EE + k)     = __floats2half2_rn(v.x, v.y);
    *(__half2*)(g_E + (size_t)r * EE + k + 2) = __floats2half2_rn(v.z, v.w);
}

// ------------------------------------------------------------------
// kernel 3b: W_ih[:, :E] -> fp16 [2048 x 256]
// ------------------------------------------------------------------
__global__ void k_convW(const float* __restrict__ W_ih)
{
    int e = (blockIdx.x * 256 + threadIdx.x) * 4;
    int n = e >> 8, k = e & 255;
    float4 v = *(const float4*)(W_ih + (size_t)n * XW + k);
    *(__half2*)(g_Wih16 + (size_t)n * EE + k)     = __floats2half2_rn(v.x, v.y);
    *(__half2*)(g_Wih16 + (size_t)n * EE + k + 2) = __floats2half2_rn(v.z, v.w);
}

// ------------------------------------------------------------------
// kernel 3b2: W_ih[:, E:] -> fp16 [2048 x 1024]
// ------------------------------------------------------------------
__global__ void k_convWb(const float* __restrict__ W_ih)
{
    int e = (blockIdx.x * 256 + threadIdx.x) * 4;
    int n = e >> 10, k = e & 1023;
    float4 v = *(const float4*)(W_ih + (size_t)n * XW + EE + k);
    *(__half2*)(g_Wihb + (size_t)n * 1024 + k)     = __floats2half2_rn(v.x, v.y);
    *(__half2*)(g_Wihb + (size_t)n * 1024 + k + 2) = __floats2half2_rn(v.z, v.w);
}

// ------------------------------------------------------------------
// kernel 3c: W_hh -> fp16 [2048 x 512]
// ------------------------------------------------------------------
__global__ void k_convWhh(const float* __restrict__ W_hh)
{
    int e = (blockIdx.x * 256 + threadIdx.x) * 4;
    float4 v = *(const float4*)(W_hh + e);
    *(__half2*)(g_Whh16 + e)     = __floats2half2_rn(v.x, v.y);
    *(__half2*)(g_Whh16 + e + 2) = __floats2half2_rn(v.z, v.w);
}

// ------------------------------------------------------------------
// kernel 3d: Wv -> fp16 (padded), 4 elems/thread
// ------------------------------------------------------------------
__global__ void k_convB(const float* __restrict__ Wv)
{
    size_t e = ((size_t)blockIdx.x * 256 + threadIdx.x) * 4;
    int n = (int)(e >> 9);
    if (n < VV) {
        float4 v = *(const float4*)(Wv + e);
        *(__half2*)(g_Bh + e)     = __floats2half2_rn(v.x, v.y);
        *(__half2*)(g_Bh + e + 2) = __floats2half2_rn(v.z, v.w);
    } else {
        *(__half2*)(g_Bh + e)     = __floats2half2_rn(0.f, 0.f);
        *(__half2*)(g_Bh + e + 2) = __floats2half2_rn(0.f, 0.f);
    }
}

// ------------------------------------------------------------------
// mma / ldmatrix / cp.async helpers
// ------------------------------------------------------------------
__device__ __forceinline__ void cp_async16(uint32_t dst, const void* src)
{
    asm volatile("cp.async.cg.shared.global [%0], [%1], 16;" :: "r"(dst), "l"(src));
}
__device__ __forceinline__ void cp_commit()
{
    asm volatile("cp.async.commit_group;");
}
__device__ __forceinline__ void cp_wait_all()
{
    asm volatile("cp.async.wait_group 0;");
}
__device__ __forceinline__ void ldsm_x4(uint32_t& r0, uint32_t& r1,
                                        uint32_t& r2, uint32_t& r3, uint32_t addr)
{
    asm volatile("ldmatrix.sync.aligned.m8n8.x4.shared.b16 {%0,%1,%2,%3}, [%4];"
                 : "=r"(r0), "=r"(r1), "=r"(r2), "=r"(r3) : "r"(addr));
}
__device__ __forceinline__ void ldsm_x2(uint32_t& r0, uint32_t& r1, uint32_t addr)
{
    asm volatile("ldmatrix.sync.aligned.m8n8.x2.shared.b16 {%0,%1}, [%2];"
                 : "=r"(r0), "=r"(r1) : "r"(addr));
}
__device__ __forceinline__ void mma16816(float& c0, float& c1, float& c2, float& c3,
                                         uint32_t a0, uint32_t a1, uint32_t a2, uint32_t a3,
                                         uint32_t b0, uint32_t b1)
{
    asm volatile("mma.sync.aligned.m16n8k16.row.col.f32.f16.f16.f32 "
                 "{%0,%1,%2,%3}, {%4,%5,%6,%7}, {%8,%9}, {%0,%1,%2,%3};"
                 : "+f"(c0), "+f"(c1), "+f"(c2), "+f"(c3)
                 : "r"(a0), "r"(a1), "r"(a2), "r"(a3), "r"(b0), "r"(b1));
}

__device__ __forceinline__ float fsigm(float x)
{
    x = fminf(fmaxf(x, -30.f), 30.f);
    return __fdividef(1.f, 1.f + __expf(-x));
}
__device__ __forceinline__ float ftanh(float x)
{
    x = fminf(fmaxf(x, -15.f), 15.f);
    float e = __expf(2.f * x);
    return __fdividef(e - 1.f, e + 1.f);
}

// ------------------------------------------------------------------
// kernel 4: sequential LSTM via HMMA. 32 CTAs x 512 threads.
// CTA c owns h-cols [16c,16c+16) => 64 gate rows (n = g*512 + 16c + j).
// Warp w: gate mi = w>>2 (16 rows), batch octet ni = w&3.
// Gate exchange via SMEM; gate math: thread (j = tid&15, b = tid>>4),
// c-state in that thread's register.
// SMEM: sW 64x1040 (66560) | sH 32x1040 (33280) | sGate 64x33 f32 (8448)
//       | sG prefetch 2x8192
// ------------------------------------------------------------------
#define SW_OFF  0
#define SH_OFF  66560
#define SGT_OFF 99840
#define SG_OFF  108288
#define LSTM_SMEM 124672
#define NCTA 32

__global__ void __launch_bounds__(512, 1) k_lstm()
{
    extern __shared__ __align__(16) char smem[];
    uint32_t sbase = (uint32_t)__cvta_generic_to_shared(smem);
    float* sGT = (float*)(smem + SGT_OFF);
    __shared__ unsigned sGen;

    const int tid  = threadIdx.x;
    const int lane = tid & 31;
    const int w    = tid >> 5;          // 0..15
    const int c    = blockIdx.x;        // 0..31
    const int mi   = w >> 2;            // gate index 0..3
    const int ni   = w & 3;             // batch octet

    // ---- load W slice: 64 rows x 512 halves ----
    #pragma unroll
    for (int i = 0; i < 8; i++) {
        int idx = tid + i * 512;        // 0..4095
        int lr = idx >> 6, seg = idx & 63;
        int n  = (lr >> 4) * HH + c * 16 + (lr & 15);
        cp_async16(sbase + SW_OFF + lr * 1040 + seg * 16,
                   g_Whh16 + (size_t)n * HH + seg * 8);
    }
    cp_commit(); cp_wait_all();

    // ---- per-thread c-state: (j, b) ----
    const int j  = tid & 15;
    const int bb = tid >> 4;            // 0..31
    float cs = g_c0[bb * HH + c * 16 + j];

    if (tid == 0) sGen = g_bar_gen;
    __syncthreads();
    const unsigned base_gen = sGen;

    // ldsm lane offsets
    const int amat = lane >> 3;
    const uint32_t aoff = sbase + SW_OFF
        + (uint32_t)((mi * 16 + (amat & 1) * 8 + (lane & 7)) * 1040
                     + ((amat >> 1) * 8) * 2);
    const uint32_t boff = sbase + SH_OFF
        + (uint32_t)((ni * 8 + (lane & 7)) * 1040 + (lane >> 3) * 16);

    // G staging identity: chunk tid -> (b = tid>>4, g = (tid&15)>>2, j4 = tid&3)
    const int gb = tid >> 4, gg_ = (tid & 15) >> 2, gj4 = tid & 3;

    // prologue: prefetch G(0) into buffer 0
    cp_async16(sbase + SG_OFF + tid * 16,
               g_G + (size_t)gb * G4 + gg_ * HH + c * 16 + gj4 * 4);
    cp_commit();

    for (int t = 0; t < TT; t++) {
        // ---- stage h cooperatively: 32 rows x 512 halves ----
        {
            const __half* hsrc = g_h16 + (size_t)t * (BQ * HH);
            #pragma unroll
            for (int i = 0; i < 4; i++) {
                int idx = tid + i * 512;        // 0..2047
                int row = idx >> 6, seg = idx & 63;
                cp_async16(sbase + SH_OFF + row * 1040 + seg * 16,
                           hsrc + (size_t)row * HH + seg * 8);
            }
            cp_commit();                        // group h(t)
        }
        // ---- prefetch G(t+1) ----
        if (t + 1 < TT) {
            cp_async16(sbase + SG_OFF + ((t + 1) & 1) * 8192 + tid * 16,
                       g_G + (size_t)((t + 1) * BQ + gb) * G4 + gg_ * HH + c * 16 + gj4 * 4);
            cp_commit();
            asm volatile("cp.async.wait_group 1;");   // h(t), G(t) retired
        } else {
            asm volatile("cp.async.wait_group 0;");
        }
        __syncthreads();                        // h visible to all warps

        // ---- MMA: warp computes C[16 rows of gate mi][8 batch] ----
        float acc[4][4];
        #pragma unroll
        for (int s = 0; s < 4; s++)
            { acc[s][0] = 0.f; acc[s][1] = 0.f; acc[s][2] = 0.f; acc[s][3] = 0.f; }

        #pragma unroll
        for (int i = 0; i < 16; i++) {
            uint32_t b0, b1, b2, b3;
            ldsm_x4(b0, b1, b2, b3, boff + i * 64);
            uint32_t a0, a1, a2, a3;
            ldsm_x4(a0, a1, a2, a3, aoff + (2 * i) * 32);
            int s0 = (2 * i) & 3;
            mma16816(acc[s0][0], acc[s0][1], acc[s0][2], acc[s0][3],
                     a0, a1, a2, a3, b0, b1);
            ldsm_x4(a0, a1, a2, a3, aoff + (2 * i + 1) * 32);
            int s1 = (2 * i + 1) & 3;
            mma16816(acc[s1][0], acc[s1][1], acc[s1][2], acc[s1][3],
                     a0, a1, a2, a3, b2, b3);
        }
        float g0 = (acc[0][0] + acc[1][0]) + (acc[2][0] + acc[3][0]);
        float g1 = (acc[0][1] + acc[1][1]) + (acc[2][1] + acc[3][1]);
        float g2 = (acc[0][2] + acc[1][2]) + (acc[2][2] + acc[3][2]);
        float g3 = (acc[0][3] + acc[1][3]) + (acc[2][3] + acc[3][3]);

        // ---- write gates to SMEM: sGT[(gate*16 + row)*33 + batch] ----
        {
            int r0 = lane >> 2, cb = ni * 8 + (lane & 3) * 2;
            sGT[(mi * 16 + r0) * 33 + cb]         = g0;
            sGT[(mi * 16 + r0) * 33 + cb + 1]     = g1;
            sGT[(mi * 16 + r0 + 8) * 33 + cb]     = g2;
            sGT[(mi * 16 + r0 + 8) * 33 + cb + 1] = g3;
        }
        __syncthreads();

        // ---- gate math: thread (j, bb) ----
        {
            const float* sGc = (const float*)(smem + SG_OFF + (t & 1) * 8192);
            int gchunk = bb * 16 + (j >> 2);
            float iv = sGT[(0 * 16 + j) * 33 + bb] + sGc[(gchunk + 0 * 4) * 4 + (j & 3)];
            float fv = sGT[(1 * 16 + j) * 33 + bb] + sGc[(gchunk + 1 * 4) * 4 + (j & 3)];
            float gv = sGT[(2 * 16 + j) * 33 + bb] + sGc[(gchunk + 2 * 4) * 4 + (j & 3)];
            float ov = sGT[(3 * 16 + j) * 33 + bb] + sGc[(gchunk + 3 * 4) * 4 + (j & 3)];
            float iS = fsigm(iv), fS = fsigm(fv), gT = ftanh(gv), oS = fsigm(ov);
            cs = fS * cs + iS * gT;
            float h = oS * ftanh(cs);
            g_h16[(size_t)(t + 1) * (BQ * HH) + bb * HH + c * 16 + j] = __float2half_rn(h);
        }

        // ---- grid barrier (32 arrivals) ----
        __threadfence();
        __syncthreads();
        if (tid == 0) {
            unsigned target = base_gen + (unsigned)(t + 1);
            unsigned arr = atomicAdd(&g_bar_count, 1u);
            if (arr == NCTA - 1u) {
                g_bar_count = 0u;
                __threadfence();
                atomicExch(&g_bar_gen, target);
            } else {
                volatile unsigned* vg = &g_bar_gen;
                while (*vg < target) { }
            }
            __threadfence();
        }
        __syncthreads();
    }
}

#define MMA_SMEM_BUF 20480           // A(10240) + B(10240) per buffer

// ------------------------------------------------------------------
// kernel 5: G = E @ Wih^T + base  (fp16 HMMA, K=256)
// ------------------------------------------------------------------
__device__ __forceinline__ void g_load_tile(
    int kt, int buf, int tid, int mtb, int ntb, uint32_t sbase)
{
    const int k0 = kt * 32;
    const uint32_t abase = sbase + buf * MMA_SMEM_BUF;
    const uint32_t bbase = abase + 10240;
    #pragma unroll
    for (int i = 0; i < 2; i++) {
        int ch  = tid + i * 256;
        int row = ch >> 2, kc = ch & 3;
        cp_async16(abase + row * 80 + kc * 16,
                   g_E + (size_t)(mtb * 128 + row) * EE + k0 + kc * 8);
        cp_async16(bbase + row * 80 + kc * 16,
                   g_Wih16 + (size_t)(ntb * 128 + row) * EE + k0 + kc * 8);
    }
    cp_commit();
}

__global__ void __launch_bounds__(256) k_G_mma()
{
    __shared__ __align__(16) unsigned char smem[2 * MMA_SMEM_BUF];
    const int tid  = threadIdx.x;
    const int lane = tid & 31;
    const int warp = tid >> 5;
    const int ntb  = blockIdx.x;     // 0..15
    const int mtb  = blockIdx.y;     // 0..31

    const int wm = (warp >> 2) * 64;
    const int wn = (warp & 3) * 32;

    uint32_t sbase = (uint32_t)__cvta_generic_to_shared(smem);

    float acc[4][4][4];
    #pragma unroll
    for (int i = 0; i < 4; i++)
        #pragma unroll
        for (int jj = 0; jj < 4; jj++) {
            acc[i][jj][0] = 0.f; acc[i][jj][1] = 0.f;
            acc[i][jj][2] = 0.f; acc[i][jj][3] = 0.f;
        }

    const int amat  = lane >> 3;
    const uint32_t a_lane_off = (uint32_t)((wm + (amat & 1) * 8 + (lane & 7)) * 80
                                           + ((amat >> 1) * 8) * 2);
    const int blane = lane & 15;
    const uint32_t b_lane_off = (uint32_t)(10240 + (wn + (blane & 7)) * 80
                                           + ((blane >> 3) * 8) * 2);

    const int NKT = 8;                         // 256 / 32
    g_load_tile(0, 0, tid, mtb, ntb, sbase);

    for (int kt = 0; kt < NKT; kt++) {
        if (kt + 1 < NKT) {
            g_load_tile(kt + 1, (kt + 1) & 1, tid, mtb, ntb, sbase);
            asm volatile("cp.async.wait_group 1;");
        } else {
            asm volatile("cp.async.wait_group 0;");
        }
        __syncthreads();

        const uint32_t abase = sbase + (kt & 1) * MMA_SMEM_BUF;
        #pragma unroll
        for (int k16 = 0; k16 < 2; k16++) {
            uint32_t af[4][4];
            uint32_t bf[4][2];
            #pragma unroll
            for (int mt = 0; mt < 4; mt++) {
                uint32_t ad = abase + a_lane_off + mt * (16 * 80) + k16 * 32;
                ldsm_x4(af[mt][0], af[mt][1], af[mt][2], af[mt][3], ad);
            }
            #pragma unroll
            for (int nt = 0; nt < 4; nt++) {
                uint32_t bd = abase + b_lane_off + nt * (8 * 80) + k16 * 32;
                ldsm_x2(bf[nt][0], bf[nt][1], bd);
            }
            #pragma unroll
            for (int mt = 0; mt < 4; mt++)
                #pragma unroll
                for (int nt = 0; nt < 4; nt++)
                    mma16816(acc[mt][nt][0], acc[mt][nt][1],
                             acc[mt][nt][2], acc[mt][nt][3],
                             af[mt][0], af[mt][1], af[mt][2], af[mt][3],
                             bf[nt][0], bf[nt][1]);
        }
        __syncthreads();
    }

    #pragma unroll
    for (int mt = 0; mt < 4; mt++) {
        #pragma unroll
        for (int nt = 0; nt < 4; nt++) {
            int col = ntb * 128 + wn + nt * 8 + (lane & 3) * 2;
            int m0 = mtb * 128 + wm + mt * 16 + (lane >> 2);
            float2 bs0 = *(const float2*)&g_base[(m0 & 31) * G4 + col];
            float2 v0 = { acc[mt][nt][0] + bs0.x, acc[mt][nt][1] + bs0.y };
            *(float2*)&g_G[(size_t)m0 * G4 + col] = v0;
            int m1 = m0 + 8;
            float2 bs1 = *(const float2*)&g_base[(m1 & 31) * G4 + col];
            float2 v1 = { acc[mt][nt][2] + bs1.x, acc[mt][nt][3] + bs1.y };
            *(float2*)&g_G[(size_t)m1 * G4 + col] = v1;
        }
    }
}

// ------------------------------------------------------------------
// kernel 5b: base = X @ Wihb^T + b_ih + b_hh  (fp16 HMMA, M=128 pad, K=1024)
// ------------------------------------------------------------------
__device__ __forceinline__ void base_load_tile(
    int kt, int buf, int tid, int ntb, uint32_t sbase)
{
    const int k0 = kt * 32;
    const uint32_t abase = sbase + buf * MMA_SMEM_BUF;
    const uint32_t bbase = abase + 10240;
    #pragma unroll
    for (int i = 0; i < 2; i++) {
        int ch  = tid + i * 256;
        int row = ch >> 2, kc = ch & 3;
        cp_async16(abase + row * 80 + kc * 16,
                   g_X16 + (size_t)row * 1024 + k0 + kc * 8);
        cp_async16(bbase + row * 80 + kc * 16,
                   g_Wihb + (size_t)(ntb * 128 + row) * 1024 + k0 + kc * 8);
    }
    cp_commit();
}

__global__ void __launch_bounds__(256) k_base_mma(const float* __restrict__ b_ih,
                                                  const float* __restrict__ b_hh)
{
    __shared__ __align__(16) unsigned char smem[2 * MMA_SMEM_BUF];
    const int tid  = threadIdx.x;
    const int lane = tid & 31;
    const int warp = tid >> 5;
    const int ntb  = blockIdx.x;     // 0..15

    const int wm = (warp >> 2) * 64;
    const int wn = (warp & 3) * 32;

    uint32_t sbase = (uint32_t)__cvta_generic_to_shared(smem);

    float acc[4][4][4];
    #pragma unroll
    for (int i = 0; i < 4; i++)
        #pragma unroll
        for (int jj = 0; jj < 4; jj++) {
            acc[i][jj][0] = 0.f; acc[i][jj][1] = 0.f;
            acc[i][jj][2] = 0.f; acc[i][jj][3] = 0.f;
        }

    const int amat  = lane >> 3;
    const uint32_t a_lane_off = (uint32_t)((wm + (amat & 1) * 8 + (lane & 7)) * 80
                                           + ((amat >> 1) * 8) * 2);
    const int blane = lane & 15;
    const uint32_t b_lane_off = (uint32_t)(10240 + (wn + (blane & 7)) * 80
                                           + ((blane >> 3) * 8) * 2);

    const int NKT = 32;                        // 1024 / 32
    base_load_tile(0, 0, tid, ntb, sbase);

    for (int kt = 0; kt < NKT; kt++) {
        if (kt + 1 < NKT) {
            base_load_tile(kt + 1, (kt + 1) & 1, tid, ntb, sbase);
            asm volatile("cp.async.wait_group 1;");
        } else {
            asm volatile("cp.async.wait_group 0;");
        }
        __syncthreads();

        const uint32_t abase = sbase + (kt & 1) * MMA_SMEM_BUF;
        #pragma unroll
        for (int k16 = 0; k16 < 2; k16++) {
            uint32_t af[4][4];
            uint32_t bf[4][2];
            #pragma unroll
            for (int mt = 0; mt < 4; mt++) {
                uint32_t ad = abase + a_lane_off + mt * (16 * 80) + k16 * 32;
                ldsm_x4(af[mt][0], af[mt][1], af[mt][2], af[mt][3], ad);
            }
            #pragma unroll
            for (int nt = 0; nt < 4; nt++) {
                uint32_t bd = abase + b_lane_off + nt * (8 * 80) + k16 * 32;
                ldsm_x2(bf[nt][0], bf[nt][1], bd);
            }
            #pragma unroll
            for (int mt = 0; mt < 4; mt++)
                #pragma unroll
                for (int nt = 0; nt < 4; nt++)
                    mma16816(acc[mt][nt][0], acc[mt][nt][1],
                             acc[mt][nt][2], acc[mt][nt][3],
                             af[mt][0], af[mt][1], af[mt][2], af[mt][3],
                             bf[nt][0], bf[nt][1]);
        }
        __syncthreads();
    }

    #pragma unroll
    for (int mt = 0; mt < 4; mt++) {
        #pragma unroll
        for (int nt = 0; nt < 4; nt++) {
            int col = ntb * 128 + wn + nt * 8 + (lane & 3) * 2;
            float bb0 = __ldg(b_ih + col) + __ldg(b_hh + col);
            float bb1 = __ldg(b_ih + col + 1) + __ldg(b_hh + col + 1);
            int m0 = wm + mt * 16 + (lane >> 2);
            if (m0 < BQ) {
                float2 v0 = { acc[mt][nt][0] + bb0, acc[mt][nt][1] + bb1 };
                *(float2*)&g_base[m0 * G4 + col] = v0;
            }
            int m1 = m0 + 8;
            if (m1 < BQ) {
                float2 v1 = { acc[mt][nt][2] + bb0, acc[mt][nt][3] + bb1 };
                *(float2*)&g_base[m1 * G4 + col] = v1;
            }
        }
    }
}

// ------------------------------------------------------------------
// kernel 6: logits via fp16 HMMA, single pass (K = 512)
// ------------------------------------------------------------------
__device__ __forceinline__ void logits_load_tile(
    int kt, int buf, int tid, int mtb, int ntb, uint32_t sbase)
{
    const int k0 = kt * 32;
    const __half* A = g_h16 + BQ * HH;
    const uint32_t abase = sbase + buf * MMA_SMEM_BUF;
    const uint32_t bbase = abase + 10240;
    #pragma unroll
    for (int i = 0; i < 2; i++) {
        int ch  = tid + i * 256;
        int row = ch >> 2, kc = ch & 3;
        cp_async16(abase + row * 80 + kc * 16,
                   A + (size_t)(mtb * 128 + row) * HH + k0 + kc * 8);
        cp_async16(bbase + row * 80 + kc * 16,
                   g_Bh + (size_t)(ntb * 128 + row) * HH + k0 + kc * 8);
    }
    cp_commit();
}

__global__ void __launch_bounds__(256) k_logits_mma(const float* __restrict__ bv,
                                                    float* __restrict__ out)
{
    __shared__ __align__(16) unsigned char smem[2 * MMA_SMEM_BUF];
    const int tid  = threadIdx.x;
    const int lane = tid & 31;
    const int warp = tid >> 5;
    const int ntb  = blockIdx.x;     // 0..78
    const int mtb  = blockIdx.y;     // 0..31

    const int wm = (warp >> 2) * 64;
    const int wn = (warp & 3) * 32;

    uint32_t sbase = (uint32_t)__cvta_generic_to_shared(smem);

    float acc[4][4][4];
    #pragma unroll
    for (int i = 0; i < 4; i++)
        #pragma unroll
        for (int jj = 0; jj < 4; jj++) {
            acc[i][jj][0] = 0.f; acc[i][jj][1] = 0.f;
            acc[i][jj][2] = 0.f; acc[i][jj][3] = 0.f;
        }

    const int amat  = lane >> 3;
    const uint32_t a_lane_off = (uint32_t)((wm + (amat & 1) * 8 + (lane & 7)) * 80
                                           + ((amat >> 1) * 8) * 2);
    const int blane = lane & 15;
    const uint32_t b_lane_off = (uint32_t)(10240 + (wn + (blane & 7)) * 80
                                           + ((blane >> 3) * 8) * 2);

    const int NKT = 16;                        // 512 / 32
    logits_load_tile(0, 0, tid, mtb, ntb, sbase);

    for (int kt = 0; kt < NKT; kt++) {
        if (kt + 1 < NKT) {
            logits_load_tile(kt + 1, (kt + 1) & 1, tid, mtb, ntb, sbase);
            asm volatile("cp.async.wait_group 1;");
        } else {
            asm volatile("cp.async.wait_group 0;");
        }
        __syncthreads();

        const uint32_t abase = sbase + (kt & 1) * MMA_SMEM_BUF;
        #pragma unroll
        for (int k16 = 0; k16 < 2; k16++) {
            uint32_t af[4][4];
            uint32_t bf[4][2];
            #pragma unroll
            for (int mt = 0; mt < 4; mt++) {
                uint32_t ad = abase + a_lane_off + mt * (16 * 80) + k16 * 32;
                ldsm_x4(af[mt][0], af[mt][1], af[mt][2], af[mt][3], ad);
            }
            #pragma unroll
            for (int nt = 0; nt < 4; nt++) {
                uint32_t bd = abase + b_lane_off + nt * (8 * 80) + k16 * 32;
                ldsm_x2(bf[nt][0], bf[nt][1], bd);
            }
            #pragma unroll
            for (int mt = 0; mt < 4; mt++)
                #pragma unroll
                for (int nt = 0; nt < 4; nt++)
                    mma16816(acc[mt][nt][0], acc[mt][nt][1],
                             acc[mt][nt][2], acc[mt][nt][3],
                             af[mt][0], af[mt][1], af[mt][2], af[mt][3],
                             bf[nt][0], bf[nt][1]);
        }
        __syncthreads();
    }

    #pragma unroll
    for (int mt = 0; mt < 4; mt++) {
        #pragma unroll
        for (int nt = 0; nt < 4; nt++) {
            int col = ntb * 128 + wn + nt * 8 + (lane & 3) * 2;
            if (col < VV) {
                float bb0 = __ldg(bv + col);
                float bb1 = __ldg(bv + col + 1);
                int m0 = mtb * 128 + wm + mt * 16 + (lane >> 2);
                int bI = m0 & 31, tI = m0 >> 5;
                float2 v0 = { acc[mt][nt][0] + bb0, acc[mt][nt][1] + bb1 };
                *(float2*)(out + (size_t)bI * TT * VV + (size_t)tI * VV + col) = v0;
                int m1 = m0 + 8;
                bI = m1 & 31; tI = m1 >> 5;
                float2 v1 = { acc[mt][nt][2] + bb0, acc[mt][nt][3] + bb1 };
                *(float2*)(out + (size_t)bI * TT * VV + (size_t)tI * VV + col) = v1;
            }
        }
    }
}

// ------------------------------------------------------------------
extern "C" void kernel_launch(void* const* d_in, const int* in_sizes, int n_in,
                              void* d_out, int out_size)
{
    const float* tv    = (const float*)d_in[0];
    const int*   texts = (const int*)  d_in[1];
    const int*   start = (const int*)  d_in[3];
    const float* emb   = (const float*)d_in[4];
    const float* W_ih  = (const float*)d_in[5];
    const float* b_ih  = (const float*)d_in[6];
    const float* W_hh  = (const float*)d_in[7];
    const float* b_hh  = (const float*)d_in[8];
    const float* Wo_w  = (const float*)d_in[9];
    const float* Wo_b  = (const float*)d_in[10];
    const float* Wh_w  = (const float*)d_in[11];
    const float* Wh_b  = (const float*)d_in[12];
    const float* Wc_w  = (const float*)d_in[13];
    const float* Wc_b  = (const float*)d_in[14];
    const float* Wv_w  = (const float*)d_in[15];
    const float* Wv_b  = (const float*)d_in[16];
    float* out = (float*)d_out;

    cudaFuncSetAttribute(k_lstm, cudaFuncAttributeMaxDynamicSharedMemorySize, LSTM_SMEM);

    k_init<<<6144, 256>>>(tv, Wo_w, Wo_b, Wh_w, Wh_b, Wc_w, Wc_b);
    k_gather<<<TT * BQ, 64>>>(emb, texts, start);
    k_convW<<<(G4 * EE) / 1024, 256>>>(W_ih);
    k_convWb<<<(G4 * 1024) / 1024, 256>>>(W_ih);
    k_convWhh<<<(G4 * HH) / 1024, 256>>>(W_hh);
    k_convB<<<(VPAD * HH) / 1024, 256>>>(Wv_w);
    k_packX<<<(BQ * 1024) / 512, 256>>>(tv);
    k_base_mma<<<16, 256>>>(b_ih, b_hh);
    k_G_mma<<<dim3(G4 / 128, (TT * BQ) / 128), 256>>>();
    k_lstm<<<NCTA, 512, LSTM_SMEM>>>();
    k_logits_mma<<<dim3(VPAD / 128, (TT * BQ) / 128), 256>>>(Wv_b, out);
}

// round 11
// speedup vs baseline: 1.2008x; 1.2008x over previous
#include <cuda_runtime.h>
#include <cuda_bf16.h>
#include <cuda_fp16.h>
#include <cstdint>
#include <math.h>

#define BQ   32
#define TT   128
#define EE   256
#define HH   512
#define ENCC 512
#define VV   10000
#define G4   2048          // 4*H
#define XW   1280          // E + H + ENC
#define VPAD 10112         // 79 * 128

// ------------------------------------------------------------------
// scratch (static device globals; no allocations allowed)
// ------------------------------------------------------------------
__device__ float g_o[BQ * HH];
__device__ float g_c0[BQ * HH];
__device__ float g_base[BQ * G4];
__device__ unsigned g_bar_count;
__device__ unsigned g_bar_gen;

// fp16 operands
__device__ __half g_G16[TT * BQ * G4];            // per-step gate input (16 MB, fp16)
__device__ __half g_h16[(TT + 1) * BQ * HH];      // slot0=h0, slot t+1 = h after step t
__device__ __half g_Bh[VPAD * HH];                // logits B (Wv) fp16
__device__ __half g_E[TT * BQ * EE];              // gathered prev-token embeddings
__device__ __half g_Wih16[G4 * EE];               // W_ih[:, :E] fp16
__device__ __half g_Wihb[G4 * 1024];              // W_ih[:, E:] fp16
__device__ __half g_Whh16[G4 * HH];               // W_hh fp16
__device__ __half g_X16[128 * 1024];              // [o|tv] fp16, rows 32..127 zero
__device__ __half g_tv16[128 * HH];               // tv fp16, rows 32..127 zero
__device__ __half g_W3h[3 * HH * HH];             // [Wo;Wh;Wc] fp16

// ------------------------------------------------------------------
// conv kernels
// ------------------------------------------------------------------
__global__ void k_convtv(const float* __restrict__ tv)
{
    int e = (blockIdx.x * 256 + threadIdx.x) * 4;   // 32*512
    float4 v = *(const float4*)(tv + e);
    *(__half2*)(g_tv16 + e)     = __floats2half2_rn(v.x, v.y);
    *(__half2*)(g_tv16 + e + 2) = __floats2half2_rn(v.z, v.w);
}

__global__ void k_convW3(const float* __restrict__ Wo,
                         const float* __restrict__ Wh,
                         const float* __restrict__ Wc)
{
    int e = (blockIdx.x * 256 + threadIdx.x) * 4;   // 3*512*512
    int n = e >> 9, k = e & 511;
    const float* src = (n < 512) ? (Wo + n * 512 + k)
                     : (n < 1024) ? (Wh + (n - 512) * 512 + k)
                                  : (Wc + (n - 1024) * 512 + k);
    float4 v = *(const float4*)src;
    *(__half2*)(g_W3h + e)     = __floats2half2_rn(v.x, v.y);
    *(__half2*)(g_W3h + e + 2) = __floats2half2_rn(v.z, v.w);
}

// ------------------------------------------------------------------
// kernel 2a: pack A = [o | tv] fp16 into g_X16 rows 0..31
// ------------------------------------------------------------------
__global__ void k_packX(const float* __restrict__ tv)
{
    int e = (blockIdx.x * 256 + threadIdx.x) * 2;    // 32x1024 elems
    int b = e >> 10, c = e & 1023;
    float v0, v1;
    if (c < 512) { v0 = g_o[b * HH + c];        v1 = g_o[b * HH + c + 1]; }
    else         { v0 = tv[b * ENCC + c - 512]; v1 = tv[b * ENCC + c - 511]; }
    *(__half2*)(g_X16 + b * 1024 + c) = __floats2half2_rn(v0, v1);
}

// ------------------------------------------------------------------
// kernel 3a: gather prev-token embeddings as dense fp16 A [4096 x 256]
// ------------------------------------------------------------------
__global__ void k_gather(const float* __restrict__ emb,
                         const int*   __restrict__ texts,
                         const int*   __restrict__ startp)
{
    int r = blockIdx.x;                 // 0..4095
    int t = r >> 5, b = r & 31;
    int tok = (t == 0) ? startp[0] : texts[b * TT + t - 1];
    const float* src = emb + (size_t)tok * EE;
    int k = threadIdx.x * 4;            // 64 threads x 4
    float4 v = *(const float4*)(src + k);
    *(__half2*)(g_E + (size_t)r * EE + k)     = __floats2half2_rn(v.x, v.y);
    *(__half2*)(g_E + (size_t)r * EE + k + 2) = __floats2half2_rn(v.z, v.w);
}

// ------------------------------------------------------------------
// kernel 3b: W_ih[:, :E] -> fp16 [2048 x 256]
// ------------------------------------------------------------------
__global__ void k_convW(const float* __restrict__ W_ih)
{
    int e = (blockIdx.x * 256 + threadIdx.x) * 4;
    int n = e >> 8, k = e & 255;
    float4 v = *(const float4*)(W_ih + (size_t)n * XW + k);
    *(__half2*)(g_Wih16 + (size_t)n * EE + k)     = __floats2half2_rn(v.x, v.y);
    *(__half2*)(g_Wih16 + (size_t)n * EE + k + 2) = __floats2half2_rn(v.z, v.w);
}

// ------------------------------------------------------------------
// kernel 3b2: W_ih[:, E:] -> fp16 [2048 x 1024]
// ------------------------------------------------------------------
__global__ void k_convWb(const float* __restrict__ W_ih)
{
    int e = (blockIdx.x * 256 + threadIdx.x) * 4;
    int n = e >> 10, k = e & 1023;
    float4 v = *(const float4*)(W_ih + (size_t)n * XW + EE + k);
    *(__half2*)(g_Wihb + (size_t)n * 1024 + k)     = __floats2half2_rn(v.x, v.y);
    *(__half2*)(g_Wihb + (size_t)n * 1024 + k + 2) = __floats2half2_rn(v.z, v.w);
}

// ------------------------------------------------------------------
// kernel 3c: W_hh -> fp16 [2048 x 512]
// ------------------------------------------------------------------
__global__ void k_convWhh(const float* __restrict__ W_hh)
{
    int e = (blockIdx.x * 256 + threadIdx.x) * 4;
    float4 v = *(const float4*)(W_hh + e);
    *(__half2*)(g_Whh16 + e)     = __floats2half2_rn(v.x, v.y);
    *(__half2*)(g_Whh16 + e + 2) = __floats2half2_rn(v.z, v.w);
}

// ------------------------------------------------------------------
// kernel 3d: Wv -> fp16 (padded), 4 elems/thread
// ------------------------------------------------------------------
__global__ void k_convB(const float* __restrict__ Wv)
{
    size_t e = ((size_t)blockIdx.x * 256 + threadIdx.x) * 4;
    int n = (int)(e >> 9);
    if (n < VV) {
        float4 v = *(const float4*)(Wv + e);
        *(__half2*)(g_Bh + e)     = __floats2half2_rn(v.x, v.y);
        *(__half2*)(g_Bh + e + 2) = __floats2half2_rn(v.z, v.w);
    } else {
        *(__half2*)(g_Bh + e)     = __floats2half2_rn(0.f, 0.f);
        *(__half2*)(g_Bh + e + 2) = __floats2half2_rn(0.f, 0.f);
    }
}

// ------------------------------------------------------------------
// mma / ldmatrix / cp.async helpers
// ------------------------------------------------------------------
__device__ __forceinline__ void cp_async16(uint32_t dst, const void* src)
{
    asm volatile("cp.async.cg.shared.global [%0], [%1], 16;" :: "r"(dst), "l"(src));
}
__device__ __forceinline__ void cp_async8(uint32_t dst, const void* src)
{
    asm volatile("cp.async.ca.shared.global [%0], [%1], 8;" :: "r"(dst), "l"(src));
}
__device__ __forceinline__ void cp_commit()
{
    asm volatile("cp.async.commit_group;");
}
__device__ __forceinline__ void cp_wait_all()
{
    asm volatile("cp.async.wait_group 0;");
}
__device__ __forceinline__ void ldsm_x4(uint32_t& r0, uint32_t& r1,
                                        uint32_t& r2, uint32_t& r3, uint32_t addr)
{
    asm volatile("ldmatrix.sync.aligned.m8n8.x4.shared.b16 {%0,%1,%2,%3}, [%4];"
                 : "=r"(r0), "=r"(r1), "=r"(r2), "=r"(r3) : "r"(addr));
}
__device__ __forceinline__ void ldsm_x2(uint32_t& r0, uint32_t& r1, uint32_t addr)
{
    asm volatile("ldmatrix.sync.aligned.m8n8.x2.shared.b16 {%0,%1}, [%2];"
                 : "=r"(r0), "=r"(r1) : "r"(addr));
}
__device__ __forceinline__ void mma16816(float& c0, float& c1, float& c2, float& c3,
                                         uint32_t a0, uint32_t a1, uint32_t a2, uint32_t a3,
                                         uint32_t b0, uint32_t b1)
{
    asm volatile("mma.sync.aligned.m16n8k16.row.col.f32.f16.f16.f32 "
                 "{%0,%1,%2,%3}, {%4,%5,%6,%7}, {%8,%9}, {%0,%1,%2,%3};"
                 : "+f"(c0), "+f"(c1), "+f"(c2), "+f"(c3)
                 : "r"(a0), "r"(a1), "r"(a2), "r"(a3), "r"(b0), "r"(b1));
}

__device__ __forceinline__ float fsigm(float x)
{
    x = fminf(fmaxf(x, -30.f), 30.f);
    return __fdividef(1.f, 1.f + __expf(-x));
}
__device__ __forceinline__ float ftanh(float x)
{
    x = fminf(fmaxf(x, -15.f), 15.f);
    float e = __expf(2.f * x);
    return __fdividef(e - 1.f, e + 1.f);
}

// ------------------------------------------------------------------
// kernel 4: sequential LSTM via HMMA (persistent, 128 CTAs x 128 thr)
// (R9-proven structure; only G is fp16 now: 8B/thread prefetch)
// SMEM: sW 16x1040 (16640) | sH 32x1040 (33280) | sG 2x1024
// ------------------------------------------------------------------
#define SW_OFF 0
#define SH_OFF 16640
#define SG_OFF 49920
#define LSTM_SMEM 51968

__global__ void __launch_bounds__(128, 1) k_lstm()
{
    extern __shared__ __align__(16) char smem[];
    uint32_t sbase = (uint32_t)__cvta_generic_to_shared(smem);
    __shared__ unsigned sGen;

    const int tid  = threadIdx.x;
    const int lane = tid & 31;
    const int w    = tid >> 5;          // warp 0..3
    const int p    = blockIdx.x;        // 0..127

    // ---- load W slice (16 rows x 512 halves) into SMEM ----
    for (int i = 0; i < 8; i++) {
        int idx = tid + i * 128;        // 0..1023
        int lr = idx >> 6, seg = idx & 63;
        int n  = (lr >> 2) * HH + p * 4 + (lr & 3);
        cp_async16(sbase + SW_OFF + lr * 1040 + seg * 16,
                   g_Whh16 + (size_t)n * HH + seg * 8);
    }
    cp_commit(); cp_wait_all();

    // ---- c state in registers (lanes 0-15 of each warp) ----
    const int q    = lane >> 2;                 // valid for lane<16
    const int colb = w * 8 + (lane & 3) * 2;    // batch pair base
    float cs0 = 0.f, cs1 = 0.f;
    if (lane < 16) {
        cs0 = g_c0[colb * HH + p * 4 + q];
        cs1 = g_c0[(colb + 1) * HH + p * 4 + q];
    }

    if (tid == 0) sGen = g_bar_gen;
    __syncthreads();
    const unsigned base_gen = sGen;

    // ldmatrix lane offsets
    const int amat = lane >> 3;
    const uint32_t aoff = sbase + SW_OFF
        + (uint32_t)(((amat & 1) * 8 + (lane & 7)) * 1040 + ((amat >> 1) * 8) * 2);
    const uint32_t boff = sbase + SH_OFF
        + (uint32_t)((w * 8 + (lane & 7)) * 1040 + (lane >> 3) * 16);

    // G staging identity for this thread
    const int gb_b = tid & 31, gb_g = tid >> 5;

    // ---- prologue: prefetch G(0) into buffer 0 (fp16, 8B/thread) ----
    cp_async8(sbase + SG_OFF + (gb_g * 32 + gb_b) * 8,
              g_G16 + (size_t)gb_b * G4 + gb_g * HH + p * 4);
    cp_commit();                                   // pending: {G(0)}

    for (int t = 0; t < TT; t++) {
        // ---- stage this warp's 8 h rows (critical path) ----
        {
            const __half* hsrc = g_h16 + (size_t)t * (BQ * HH);
            #pragma unroll
            for (int j = 0; j < 16; j++) {
                int idx = lane + j * 32;        // 0..511
                int row = idx >> 6, seg = idx & 63;
                cp_async16(sbase + SH_OFF + (w * 8 + row) * 1040 + seg * 16,
                           hsrc + (size_t)(w * 8 + row) * HH + seg * 8);
            }
            cp_commit();                        // group h(t)
        }
        // ---- prefetch G(t+1) (off critical path) ----
        if (t + 1 < TT) {
            cp_async8(sbase + SG_OFF + ((t + 1) & 1) * 1024 + (gb_g * 32 + gb_b) * 8,
                      g_G16 + (size_t)((t + 1) * BQ + gb_b) * G4 + gb_g * HH + p * 4);
            cp_commit();                        // group G(t+1)
            asm volatile("cp.async.wait_group 1;");   // h(t), G(t) done
        } else {
            asm volatile("cp.async.wait_group 0;");
        }
        __syncwarp();

        // ---- MMA: 32 k-steps, 4 interleaved accumulator sets ----
        float acc[4][4];
        #pragma unroll
        for (int s = 0; s < 4; s++)
            { acc[s][0] = 0.f; acc[s][1] = 0.f; acc[s][2] = 0.f; acc[s][3] = 0.f; }

        #pragma unroll
        for (int i = 0; i < 16; i++) {
            uint32_t b0, b1, b2, b3;
            ldsm_x4(b0, b1, b2, b3, boff + i * 64);
            uint32_t a0, a1, a2, a3;
            ldsm_x4(a0, a1, a2, a3, aoff + (2 * i) * 32);
            int s0 = (2 * i) & 3;
            mma16816(acc[s0][0], acc[s0][1], acc[s0][2], acc[s0][3],
                     a0, a1, a2, a3, b0, b1);
            ldsm_x4(a0, a1, a2, a3, aoff + (2 * i + 1) * 32);
            int s1 = (2 * i + 1) & 3;
            mma16816(acc[s1][0], acc[s1][1], acc[s1][2], acc[s1][3],
                     a0, a1, a2, a3, b2, b3);
        }
        float g0 = (acc[0][0] + acc[1][0]) + (acc[2][0] + acc[3][0]);
        float g1 = (acc[0][1] + acc[1][1]) + (acc[2][1] + acc[3][1]);
        float g2 = (acc[0][2] + acc[1][2]) + (acc[2][2] + acc[3][2]);
        float g3 = (acc[0][3] + acc[1][3]) + (acc[2][3] + acc[3][3]);

        __syncthreads();   // all threads' G(t) copies visible

        // ---- add G (fp16 layout: sG[(gate*32+b)*4 + q] halves) ----
        const __half* sGc = (const __half*)(smem + SG_OFF + (t & 1) * 1024);
        {
            int r0 = lane >> 2;                 // 0..7
            int gg = r0 >> 2, qq = r0 & 3;      // gate base (0 or 1), q
            g0 += __half2float(sGc[(gg * 32 + colb) * 4 + qq]);
            g1 += __half2float(sGc[(gg * 32 + colb + 1) * 4 + qq]);
            g2 += __half2float(sGc[((gg + 2) * 32 + colb) * 4 + qq]);
            g3 += __half2float(sGc[((gg + 2) * 32 + colb + 1) * 4 + qq]);
        }

        // ---- exchange f/o (lanes 16-31) -> i/g holders (lanes 0-15) ----
        float f0 = __shfl_xor_sync(0xffffffffu, g0, 16);
        float f1 = __shfl_xor_sync(0xffffffffu, g1, 16);
        float o0 = __shfl_xor_sync(0xffffffffu, g2, 16);
        float o1 = __shfl_xor_sync(0xffffffffu, g3, 16);

        if (lane < 16) {
            float i0 = fsigm(g0), i1 = fsigm(g1);
            float t0 = ftanh(g2), t1 = ftanh(g3);
            float F0 = fsigm(f0), F1 = fsigm(f1);
            float O0 = fsigm(o0), O1 = fsigm(o1);
            cs0 = F0 * cs0 + i0 * t0;
            cs1 = F1 * cs1 + i1 * t1;
            float h0 = O0 * ftanh(cs0);
            float h1 = O1 * ftanh(cs1);
            size_t hb = (size_t)(t + 1) * (BQ * HH) + p * 4 + q;
            g_h16[hb + (size_t)colb * HH]       = __float2half_rn(h0);
            g_h16[hb + (size_t)(colb + 1) * HH] = __float2half_rn(h1);
        }

        // ---- grid barrier ----
        __threadfence();
        __syncthreads();
        if (tid == 0) {
            unsigned target = base_gen + (unsigned)(t + 1);
            unsigned arr = atomicAdd(&g_bar_count, 1u);
            if (arr == 127u) {
                g_bar_count = 0u;
                __threadfence();
                atomicExch(&g_bar_gen, target);
            } else {
                volatile unsigned* vg = &g_bar_gen;
                while (*vg < target) { }
            }
            __threadfence();
        }
        __syncthreads();
    }
}

#define MMA_SMEM_BUF 20480           // A(10240) + B(10240) per buffer

// ------------------------------------------------------------------
// kernel 5: G = E @ Wih^T + base  (fp16 HMMA, K=256) -> g_G16 fp16
// ------------------------------------------------------------------
__device__ __forceinline__ void g_load_tile(
    int kt, int buf, int tid, int mtb, int ntb, uint32_t sbase)
{
    const int k0 = kt * 32;
    const uint32_t abase = sbase + buf * MMA_SMEM_BUF;
    const uint32_t bbase = abase + 10240;
    #pragma unroll
    for (int i = 0; i < 2; i++) {
        int ch  = tid + i * 256;
        int row = ch >> 2, kc = ch & 3;
        cp_async16(abase + row * 80 + kc * 16,
                   g_E + (size_t)(mtb * 128 + row) * EE + k0 + kc * 8);
        cp_async16(bbase + row * 80 + kc * 16,
                   g_Wih16 + (size_t)(ntb * 128 + row) * EE + k0 + kc * 8);
    }
    cp_commit();
}

__global__ void __launch_bounds__(256) k_G_mma()
{
    __shared__ __align__(16) unsigned char smem[2 * MMA_SMEM_BUF];
    const int tid  = threadIdx.x;
    const int lane = tid & 31;
    const int warp = tid >> 5;
    const int ntb  = blockIdx.x;     // 0..15
    const int mtb  = blockIdx.y;     // 0..31

    const int wm = (warp >> 2) * 64;
    const int wn = (warp & 3) * 32;

    uint32_t sbase = (uint32_t)__cvta_generic_to_shared(smem);

    float acc[4][4][4];
    #pragma unroll
    for (int i = 0; i < 4; i++)
        #pragma unroll
        for (int jj = 0; jj < 4; jj++) {
            acc[i][jj][0] = 0.f; acc[i][jj][1] = 0.f;
            acc[i][jj][2] = 0.f; acc[i][jj][3] = 0.f;
        }

    const int amat  = lane >> 3;
    const uint32_t a_lane_off = (uint32_t)((wm + (amat & 1) * 8 + (lane & 7)) * 80
                                           + ((amat >> 1) * 8) * 2);
    const int blane = lane & 15;
    const uint32_t b_lane_off = (uint32_t)(10240 + (wn + (blane & 7)) * 80
                                           + ((blane >> 3) * 8) * 2);

    const int NKT = 8;                         // 256 / 32
    g_load_tile(0, 0, tid, mtb, ntb, sbase);

    for (int kt = 0; kt < NKT; kt++) {
        if (kt + 1 < NKT) {
            g_load_tile(kt + 1, (kt + 1) & 1, tid, mtb, ntb, sbase);
            asm volatile("cp.async.wait_group 1;");
        } else {
            asm volatile("cp.async.wait_group 0;");
        }
        __syncthreads();

        const uint32_t abase = sbase + (kt & 1) * MMA_SMEM_BUF;
        #pragma unroll
        for (int k16 = 0; k16 < 2; k16++) {
            uint32_t af[4][4];
            uint32_t bf[4][2];
            #pragma unroll
            for (int mt = 0; mt < 4; mt++) {
                uint32_t ad = abase + a_lane_off + mt * (16 * 80) + k16 * 32;
                ldsm_x4(af[mt][0], af[mt][1], af[mt][2], af[mt][3], ad);
            }
            #pragma unroll
            for (int nt = 0; nt < 4; nt++) {
                uint32_t bd = abase + b_lane_off + nt * (8 * 80) + k16 * 32;
                ldsm_x2(bf[nt][0], bf[nt][1], bd);
            }
            #pragma unroll
            for (int mt = 0; mt < 4; mt++)
                #pragma unroll
                for (int nt = 0; nt < 4; nt++)
                    mma16816(acc[mt][nt][0], acc[mt][nt][1],
                             acc[mt][nt][2], acc[mt][nt][3],
                             af[mt][0], af[mt][1], af[mt][2], af[mt][3],
                             bf[nt][0], bf[nt][1]);
        }
        __syncthreads();
    }

    #pragma unroll
    for (int mt = 0; mt < 4; mt++) {
        #pragma unroll
        for (int nt = 0; nt < 4; nt++) {
            int col = ntb * 128 + wn + nt * 8 + (lane & 3) * 2;
            int m0 = mtb * 128 + wm + mt * 16 + (lane >> 2);
            float2 bs0 = *(const float2*)&g_base[(m0 & 31) * G4 + col];
            *(__half2*)&g_G16[(size_t)m0 * G4 + col] =
                __floats2half2_rn(acc[mt][nt][0] + bs0.x, acc[mt][nt][1] + bs0.y);
            int m1 = m0 + 8;
            float2 bs1 = *(const float2*)&g_base[(m1 & 31) * G4 + col];
            *(__half2*)&g_G16[(size_t)m1 * G4 + col] =
                __floats2half2_rn(acc[mt][nt][2] + bs1.x, acc[mt][nt][3] + bs1.y);
        }
    }
}

// ------------------------------------------------------------------
// kernel 5b: base = X @ Wihb^T + b_ih + b_hh  (fp16 HMMA, M=128 pad, K=1024)
// ------------------------------------------------------------------
__device__ __forceinline__ void base_load_tile(
    int kt, int buf, int tid, int ntb, uint32_t sbase)
{
    const int k0 = kt * 32;
    const uint32_t abase = sbase + buf * MMA_SMEM_BUF;
    const uint32_t bbase = abase + 10240;
    #pragma unroll
    for (int i = 0; i < 2; i++) {
        int ch  = tid + i * 256;
        int row = ch >> 2, kc = ch & 3;
        cp_async16(abase + row * 80 + kc * 16,
                   g_X16 + (size_t)row * 1024 + k0 + kc * 8);
        cp_async16(bbase + row * 80 + kc * 16,
                   g_Wihb + (size_t)(ntb * 128 + row) * 1024 + k0 + kc * 8);
    }
    cp_commit();
}

__global__ void __launch_bounds__(256) k_base_mma(const float* __restrict__ b_ih,
                                                  const float* __restrict__ b_hh)
{
    __shared__ __align__(16) unsigned char smem[2 * MMA_SMEM_BUF];
    const int tid  = threadIdx.x;
    const int lane = tid & 31;
    const int warp = tid >> 5;
    const int ntb  = blockIdx.x;     // 0..15

    const int wm = (warp >> 2) * 64;
    const int wn = (warp & 3) * 32;

    uint32_t sbase = (uint32_t)__cvta_generic_to_shared(smem);

    float acc[4][4][4];
    #pragma unroll
    for (int i = 0; i < 4; i++)
        #pragma unroll
        for (int jj = 0; jj < 4; jj++) {
            acc[i][jj][0] = 0.f; acc[i][jj][1] = 0.f;
            acc[i][jj][2] = 0.f; acc[i][jj][3] = 0.f;
        }

    const int amat  = lane >> 3;
    const uint32_t a_lane_off = (uint32_t)((wm + (amat & 1) * 8 + (lane & 7)) * 80
                                           + ((amat >> 1) * 8) * 2);
    const int blane = lane & 15;
    const uint32_t b_lane_off = (uint32_t)(10240 + (wn + (blane & 7)) * 80
                                           + ((blane >> 3) * 8) * 2);

    const int NKT = 32;                        // 1024 / 32
    base_load_tile(0, 0, tid, ntb, sbase);

    for (int kt = 0; kt < NKT; kt++) {
        if (kt + 1 < NKT) {
            base_load_tile(kt + 1, (kt + 1) & 1, tid, ntb, sbase);
            asm volatile("cp.async.wait_group 1;");
        } else {
            asm volatile("cp.async.wait_group 0;");
        }
        __syncthreads();

        const uint32_t abase = sbase + (kt & 1) * MMA_SMEM_BUF;
        #pragma unroll
        for (int k16 = 0; k16 < 2; k16++) {
            uint32_t af[4][4];
            uint32_t bf[4][2];
            #pragma unroll
            for (int mt = 0; mt < 4; mt++) {
                uint32_t ad = abase + a_lane_off + mt * (16 * 80) + k16 * 32;
                ldsm_x4(af[mt][0], af[mt][1], af[mt][2], af[mt][3], ad);
            }
            #pragma unroll
            for (int nt = 0; nt < 4; nt++) {
                uint32_t bd = abase + b_lane_off + nt * (8 * 80) + k16 * 32;
                ldsm_x2(bf[nt][0], bf[nt][1], bd);
            }
            #pragma unroll
            for (int mt = 0; mt < 4; mt++)
                #pragma unroll
                for (int nt = 0; nt < 4; nt++)
                    mma16816(acc[mt][nt][0], acc[mt][nt][1],
                             acc[mt][nt][2], acc[mt][nt][3],
                             af[mt][0], af[mt][1], af[mt][2], af[mt][3],
                             bf[nt][0], bf[nt][1]);
        }
        __syncthreads();
    }

    #pragma unroll
    for (int mt = 0; mt < 4; mt++) {
        #pragma unroll
        for (int nt = 0; nt < 4; nt++) {
            int col = ntb * 128 + wn + nt * 8 + (lane & 3) * 2;
            float bb0 = __ldg(b_ih + col) + __ldg(b_hh + col);
            float bb1 = __ldg(b_ih + col + 1) + __ldg(b_hh + col + 1);
            int m0 = wm + mt * 16 + (lane >> 2);
            if (m0 < BQ) {
                float2 v0 = { acc[mt][nt][0] + bb0, acc[mt][nt][1] + bb1 };
                *(float2*)&g_base[m0 * G4 + col] = v0;
            }
            int m1 = m0 + 8;
            if (m1 < BQ) {
                float2 v1 = { acc[mt][nt][2] + bb0, acc[mt][nt][3] + bb1 };
                *(float2*)&g_base[m1 * G4 + col] = v1;
            }
        }
    }
}

// ------------------------------------------------------------------
// kernel 5c: init = tv @ [Wo;Wh;Wc]^T + bias  (fp16 HMMA, M=32 pad 128, K=512)
// N block ntb: 0-3 -> o, 4-7 -> h0, 8-11 -> c0
// ------------------------------------------------------------------
__device__ __forceinline__ void init_load_tile(
    int kt, int buf, int tid, int ntb, uint32_t sbase)
{
    const int k0 = kt * 32;
    const uint32_t abase = sbase + buf * MMA_SMEM_BUF;
    const uint32_t bbase = abase + 10240;
    #pragma unroll
    for (int i = 0; i < 2; i++) {
        int ch  = tid + i * 256;
        int row = ch >> 2, kc = ch & 3;
        cp_async16(abase + row * 80 + kc * 16,
                   g_tv16 + (size_t)row * HH + k0 + kc * 8);
        cp_async16(bbase + row * 80 + kc * 16,
                   g_W3h + (size_t)(ntb * 128 + row) * HH + k0 + kc * 8);
    }
    cp_commit();
}

__global__ void __launch_bounds__(256) k_init_mma(const float* __restrict__ bo,
                                                  const float* __restrict__ bh,
                                                  const float* __restrict__ bc)
{
    __shared__ __align__(16) unsigned char smem[2 * MMA_SMEM_BUF];
    const int tid  = threadIdx.x;
    const int lane = tid & 31;
    const int warp = tid >> 5;
    const int ntb  = blockIdx.x;     // 0..11

    const int wm = (warp >> 2) * 64;
    const int wn = (warp & 3) * 32;

    uint32_t sbase = (uint32_t)__cvta_generic_to_shared(smem);

    float acc[4][4][4];
    #pragma unroll
    for (int i = 0; i < 4; i++)
        #pragma unroll
        for (int jj = 0; jj < 4; jj++) {
            acc[i][jj][0] = 0.f; acc[i][jj][1] = 0.f;
            acc[i][jj][2] = 0.f; acc[i][jj][3] = 0.f;
        }

    const int amat  = lane >> 3;
    const uint32_t a_lane_off = (uint32_t)((wm + (amat & 1) * 8 + (lane & 7)) * 80
                                           + ((amat >> 1) * 8) * 2);
    const int blane = lane & 15;
    const uint32_t b_lane_off = (uint32_t)(10240 + (wn + (blane & 7)) * 80
                                           + ((blane >> 3) * 8) * 2);

    const int NKT = 16;                        // 512 / 32
    init_load_tile(0, 0, tid, ntb, sbase);

    for (int kt = 0; kt < NKT; kt++) {
        if (kt + 1 < NKT) {
            init_load_tile(kt + 1, (kt + 1) & 1, tid, ntb, sbase);
            asm volatile("cp.async.wait_group 1;");
        } else {
            asm volatile("cp.async.wait_group 0;");
        }
        __syncthreads();

        const uint32_t abase = sbase + (kt & 1) * MMA_SMEM_BUF;
        #pragma unroll
        for (int k16 = 0; k16 < 2; k16++) {
            uint32_t af[4][4];
            uint32_t bf[4][2];
            #pragma unroll
            for (int mt = 0; mt < 4; mt++) {
                uint32_t ad = abase + a_lane_off + mt * (16 * 80) + k16 * 32;
                ldsm_x4(af[mt][0], af[mt][1], af[mt][2], af[mt][3], ad);
            }
            #pragma unroll
            for (int nt = 0; nt < 4; nt++) {
                uint32_t bd = abase + b_lane_off + nt * (8 * 80) + k16 * 32;
                ldsm_x2(bf[nt][0], bf[nt][1], bd);
            }
            #pragma unroll
            for (int mt = 0; mt < 4; mt++)
                #pragma unroll
                for (int nt = 0; nt < 4; nt++)
                    mma16816(acc[mt][nt][0], acc[mt][nt][1],
                             acc[mt][nt][2], acc[mt][nt][3],
                             af[mt][0], af[mt][1], af[mt][2], af[mt][3],
                             bf[nt][0], bf[nt][1]);
        }
        __syncthreads();
    }

    const int seg = ntb >> 2;                // 0=o, 1=h0, 2=c0
    const float* bias = (seg == 0) ? bo : (seg == 1) ? bh : bc;

    #pragma unroll
    for (int mt = 0; mt < 4; mt++) {
        #pragma unroll
        for (int nt = 0; nt < 4; nt++) {
            int cg = ntb * 128 + wn + nt * 8 + (lane & 3) * 2;
            int cs = cg & 511;
            float bb0 = __ldg(bias + cs);
            float bb1 = __ldg(bias + cs + 1);
            #pragma unroll
            for (int half2i = 0; half2i < 2; half2i++) {
                int m = wm + mt * 16 + (lane >> 2) + half2i * 8;
                if (m < BQ) {
                    float v0 = acc[mt][nt][half2i * 2 + 0] + bb0;
                    float v1 = acc[mt][nt][half2i * 2 + 1] + bb1;
                    if (seg == 0) {
                        float2 vv = { v0, v1 };
                        *(float2*)&g_o[m * HH + cs] = vv;
                    } else if (seg == 1) {
                        *(__half2*)&g_h16[m * HH + cs] = __floats2half2_rn(v0, v1);
                    } else {
                        float2 vv = { v0, v1 };
                        *(float2*)&g_c0[m * HH + cs] = vv;
                    }
                }
            }
        }
    }
}

// ------------------------------------------------------------------
// kernel 6: logits via fp16 HMMA, single pass (K = 512)
// ------------------------------------------------------------------
__device__ __forceinline__ void logits_load_tile(
    int kt, int buf, int tid, int mtb, int ntb, uint32_t sbase)
{
    const int k0 = kt * 32;
    const __half* A = g_h16 + BQ * HH;
    const uint32_t abase = sbase + buf * MMA_SMEM_BUF;
    const uint32_t bbase = abase + 10240;
    #pragma unroll
    for (int i = 0; i < 2; i++) {
        int ch  = tid + i * 256;
        int row = ch >> 2, kc = ch & 3;
        cp_async16(abase + row * 80 + kc * 16,
                   A + (size_t)(mtb * 128 + row) * HH + k0 + kc * 8);
        cp_async16(bbase + row * 80 + kc * 16,
                   g_Bh + (size_t)(ntb * 128 + row) * HH + k0 + kc * 8);
    }
    cp_commit();
}

__global__ void __launch_bounds__(256) k_logits_mma(const float* __restrict__ bv,
                                                    float* __restrict__ out)
{
    __shared__ __align__(16) unsigned char smem[2 * MMA_SMEM_BUF];
    const int tid  = threadIdx.x;
    const int lane = tid & 31;
    const int warp = tid >> 5;
    const int ntb  = blockIdx.x;     // 0..78
    const int mtb  = blockIdx.y;     // 0..31

    const int wm = (warp >> 2) * 64;
    const int wn = (warp & 3) * 32;

    uint32_t sbase = (uint32_t)__cvta_generic_to_shared(smem);

    float acc[4][4][4];
    #pragma unroll
    for (int i = 0; i < 4; i++)
        #pragma unroll
        for (int jj = 0; jj < 4; jj++) {
            acc[i][jj][0] = 0.f; acc[i][jj][1] = 0.f;
            acc[i][jj][2] = 0.f; acc[i][jj][3] = 0.f;
        }

    const int amat  = lane >> 3;
    const uint32_t a_lane_off = (uint32_t)((wm + (amat & 1) * 8 + (lane & 7)) * 80
                                           + ((amat >> 1) * 8) * 2);
    const int blane = lane & 15;
    const uint32_t b_lane_off = (uint32_t)(10240 + (wn + (blane & 7)) * 80
                                           + ((blane >> 3) * 8) * 2);

    const int NKT = 16;                        // 512 / 32
    logits_load_tile(0, 0, tid, mtb, ntb, sbase);

    for (int kt = 0; kt < NKT; kt++) {
        if (kt + 1 < NKT) {
            logits_load_tile(kt + 1, (kt + 1) & 1, tid, mtb, ntb, sbase);
            asm volatile("cp.async.wait_group 1;");
        } else {
            asm volatile("cp.async.wait_group 0;");
        }
        __syncthreads();

        const uint32_t abase = sbase + (kt & 1) * MMA_SMEM_BUF;
        #pragma unroll
        for (int k16 = 0; k16 < 2; k16++) {
            uint32_t af[4][4];
            uint32_t bf[4][2];
            #pragma unroll
            for (int mt = 0; mt < 4; mt++) {
                uint32_t ad = abase + a_lane_off + mt * (16 * 80) + k16 * 32;
                ldsm_x4(af[mt][0], af[mt][1], af[mt][2], af[mt][3], ad);
            }
            #pragma unroll
            for (int nt = 0; nt < 4; nt++) {
                uint32_t bd = abase + b_lane_off + nt * (8 * 80) + k16 * 32;
                ldsm_x2(bf[nt][0], bf[nt][1], bd);
            }
            #pragma unroll
            for (int mt = 0; mt < 4; mt++)
                #pragma unroll
                for (int nt = 0; nt < 4; nt++)
                    mma16816(acc[mt][nt][0], acc[mt][nt][1],
                             acc[mt][nt][2], acc[mt][nt][3],
                             af[mt][0], af[mt][1], af[mt][2], af[mt][3],
                             bf[nt][0], bf[nt][1]);
        }
        __syncthreads();
    }

    #pragma unroll
    for (int mt = 0; mt < 4; mt++) {
        #pragma unroll
        for (int nt = 0; nt < 4; nt++) {
            int col = ntb * 128 + wn + nt * 8 + (lane & 3) * 2;
            if (col < VV) {
                float bb0 = __ldg(bv + col);
                float bb1 = __ldg(bv + col + 1);
                int m0 = mtb * 128 + wm + mt * 16 + (lane >> 2);
                int bI = m0 & 31, tI = m0 >> 5;
                float2 v0 = { acc[mt][nt][0] + bb0, acc[mt][nt][1] + bb1 };
                *(float2*)(out + (size_t)bI * TT * VV + (size_t)tI * VV + col) = v0;
                int m1 = m0 + 8;
                bI = m1 & 31; tI = m1 >> 5;
                float2 v1 = { acc[mt][nt][2] + bb0, acc[mt][nt][3] + bb1 };
                *(float2*)(out + (size_t)bI * TT * VV + (size_t)tI * VV + col) = v1;
            }
        }
    }
}

// ------------------------------------------------------------------
extern "C" void kernel_launch(void* const* d_in, const int* in_sizes, int n_in,
                              void* d_out, int out_size)
{
    const float* tv    = (const float*)d_in[0];
    const int*   texts = (const int*)  d_in[1];
    const int*   start = (const int*)  d_in[3];
    const float* emb   = (const float*)d_in[4];
    const float* W_ih  = (const float*)d_in[5];
    const float* b_ih  = (const float*)d_in[6];
    const float* W_hh  = (const float*)d_in[7];
    const float* b_hh  = (const float*)d_in[8];
    const float* Wo_w  = (const float*)d_in[9];
    const float* Wo_b  = (const float*)d_in[10];
    const float* Wh_w  = (const float*)d_in[11];
    const float* Wh_b  = (const float*)d_in[12];
    const float* Wc_w  = (const float*)d_in[13];
    const float* Wc_b  = (const float*)d_in[14];
    const float* Wv_w  = (const float*)d_in[15];
    const float* Wv_b  = (const float*)d_in[16];
    float* out = (float*)d_out;

    cudaFuncSetAttribute(k_lstm, cudaFuncAttributeMaxDynamicSharedMemorySize, LSTM_SMEM);

    k_convtv<<<(BQ * HH) / 1024, 256>>>(tv);
    k_convW3<<<(3 * HH * HH) / 1024, 256>>>(Wo_w, Wh_w, Wc_w);
    k_gather<<<TT * BQ, 64>>>(emb, texts, start);
    k_convW<<<(G4 * EE) / 1024, 256>>>(W_ih);
    k_convWb<<<(G4 * 1024) / 1024, 256>>>(W_ih);
    k_convWhh<<<(G4 * HH) / 1024, 256>>>(W_hh);
    k_convB<<<(VPAD * HH) / 1024, 256>>>(Wv_w);
    k_init_mma<<<12, 256>>>(Wo_b, Wh_b, Wc_b);
    k_packX<<<(BQ * 1024) / 512, 256>>>(tv);
    k_base_mma<<<16, 256>>>(b_ih, b_hh);
    k_G_mma<<<dim3(G4 / 128, (TT * BQ) / 128), 256>>>();
    k_lstm<<<128, 128, LSTM_SMEM>>>();
    k_logits_mma<<<dim3(VPAD / 128, (TT * BQ) / 128), 256>>>(Wv_b, out);
}